// round 14
// baseline (speedup 1.0000x reference)
#include <cuda_runtime.h>
#include <cuda_bf16.h>
#include <stdint.h>

#define GN 512
#define GW 332
#define GH 324
#define GHW (GW * GH)
#define GC 120
#define TSX 16
#define TSY 4
#define NTX 21          // ceil(332/16)
#define NTY 81          // 324/4
#define NTILES (NTX * NTY)   // 1701
#define NBLOCKS 444     // 148 SMs x 3 CTAs: exactly one wave
#define CUT 25.0f       // 5-sigma: exp(-12.5) ~ 3.7e-6

static __device__ __forceinline__ unsigned order_float(float f) {
    unsigned u = __float_as_uint(f);
    return (u & 0x80000000u) ? ~u : (u | 0x80000000u);
}

// ---------------------------------------------------------------------------
// Persistent fused kernel. 444 blocks x 256 threads; block b serves tiles
// b, b+444, b+888, b+1332 (row-major order -> its tiles are ~21 tile-rows
// apart, so each block gets ~one hot-band tile: static load balance).
// Per block: project ALL 512 gaussians ONCE into smem (tile-independent),
// then per tile: ellipse-cull (keys only), bitonic sort by (depth, index)
// == stable argsort, permute from staged array, composite (R10-proven loop).
// ---------------------------------------------------------------------------
__global__ __launch_bounds__(256, 3) void fused_kernel(
    const float* __restrict__ pos,     // [N,3]
    const float* __restrict__ scales,  // [N,3]
    const float* __restrict__ ops,     // [N]
    const float* __restrict__ spec,    // [N,C]
    const float* __restrict__ tone,    // [C]
    const float* __restrict__ K,       // [3,3]
    const float* __restrict__ E,       // [4,4]
    float* __restrict__ out)           // [C*HW + HW + HW]
{
    __shared__ float4 a1[GN], a2[GN];           // staged projection (all 512)
    __shared__ float4 b1[GN], b2[GN];           // per-tile depth-sorted
    __shared__ unsigned long long s_key[GN];
    __shared__ float s_tone[GC];
    __shared__ int   s_cnt, s_wcnt[8];

    const int tid = threadIdx.x;
    if (tid < GC) s_tone[tid] = __ldg(tone + tid);

    // Camera matrices (uniform broadcast loads).
    float E0 = __ldg(E + 0), E1 = __ldg(E + 1), E2  = __ldg(E + 2),  E3  = __ldg(E + 3);
    float E4 = __ldg(E + 4), E5 = __ldg(E + 5), E6  = __ldg(E + 6),  E7  = __ldg(E + 7);
    float E8 = __ldg(E + 8), E9 = __ldg(E + 9), E10 = __ldg(E + 10), E11 = __ldg(E + 11);
    float K0 = __ldg(K + 0), K1 = __ldg(K + 1), K2 = __ldg(K + 2);
    float K3 = __ldg(K + 3), K4 = __ldg(K + 4), K5 = __ldg(K + 5);
    float K6 = __ldg(K + 6), K7 = __ldg(K + 7), K8 = __ldg(K + 8);

    // ---- Project all 512 gaussians ONCE (tile-independent), stage to smem ----
#pragma unroll
    for (int c = 0; c < 2; c++) {
        const int i = c * 256 + tid;
        float p0 = __ldg(pos + 3 * i + 0), p1 = __ldg(pos + 3 * i + 1), p2 = __ldg(pos + 3 * i + 2);
        float cx = E0 * p0 + E1 * p1 + E2  * p2 + E3;
        float cy = E4 * p0 + E5 * p1 + E6  * p2 + E7;
        float cz = E8 * p0 + E9 * p1 + E10 * p2 + E11;
        float prx = K0 * cx + K1 * cy + K2 * cz;
        float pry = K3 * cx + K4 * cy + K5 * cz;
        float prz = K6 * cx + K7 * cy + K8 * cz;
        float sx = prx / (prz + 1e-6f);
        float sy = pry / (prz + 1e-6f);
        float d  = cz;

        bool valid = (d > 0.01f) && (d < 100.0f) &&
                     (sx > -100.0f) && (sx < (float)GW + 100.0f) &&
                     (sy > -100.0f) && (sy < (float)GH + 100.0f);
        if (!valid) sx = 1e10f;   // pushes m_min -> huge: never kept by any tile

        float s0 = __ldg(scales + 3 * i + 0), s1v = __ldg(scales + 3 * i + 1);
        float c00 = 1.0f / (s0 * s0 + 1e-4f);
        float c11 = 1.0f / (s1v * s1v + 1e-4f);

        a1[i] = make_float4(sx, sy, c00, c11);
        a2[i] = make_float4(__ldg(ops + i), d, __int_as_float(i), 0.0f);
    }
    __syncthreads();

    // ---- Loop over this block's tiles (strided: static balance) ----
    for (int t = blockIdx.x; t < NTILES; t += NBLOCKS) {
        const int x0 = (t % NTX) * TSX;
        const int y0 = (t / NTX) * TSY;
        const float fx0 = (float)x0, fx1 = (float)(x0 + TSX - 1);
        const float fy0 = (float)y0, fy1 = (float)(y0 + TSY - 1);

        if (tid == 0) s_cnt = 0;
        __syncthreads();

        // ---- Ellipse cull: emit (depth, index) keys only (stable order) ----
#pragma unroll
        for (int c = 0; c < 2; c++) {
            const int i = c * 256 + tid;
            float4 f1 = a1[i];
            // exact min mahalanobis over the tile rect
            float nx = fminf(fmaxf(f1.x, fx0), fx1);
            float ny = fminf(fmaxf(f1.y, fy0), fy1);
            float ddx = f1.x - nx, ddy = f1.y - ny;
            float m_min = ddx * ddx * f1.z + ddy * ddy * f1.w;
            bool keep = (m_min < CUT);

            unsigned bm = __ballot_sync(0xffffffffu, keep);
            int lane = tid & 31, w = tid >> 5;
            if (lane == 0) s_wcnt[w] = __popc(bm);
            __syncthreads();
            int woff = 0;
#pragma unroll
            for (int ww = 0; ww < 8; ww++)
                if (ww < w) woff += s_wcnt[ww];
            if (keep) {
                int p = s_cnt + woff + __popc(bm & ((1u << lane) - 1u));
                s_key[p] = ((unsigned long long)order_float(a2[i].y) << 32) | (unsigned)i;
            }
            __syncthreads();
            if (tid == 0) {
                int tt = 0;
#pragma unroll
                for (int ww = 0; ww < 8; ww++) tt += s_wcnt[ww];
                s_cnt += tt;
            }
            __syncthreads();
        }
        const int cnt = s_cnt;

        // ---- Local bitonic sort by (depth, index) ----
        int p2 = 1;
        while (p2 < cnt) p2 <<= 1;
        for (int p = cnt + tid; p < p2; p += 256)
            s_key[p] = 0xffffffffffffffffull;
        __syncthreads();
        for (int k = 2; k <= p2; k <<= 1) {
            for (int j = k >> 1; j > 0; j >>= 1) {
                if (tid < (p2 >> 1)) {
                    int i = ((tid & ~(j - 1)) << 1) | (tid & (j - 1));
                    int ixj = i | j;
                    unsigned long long va = s_key[i], vb = s_key[ixj];
                    bool asc = ((i & k) == 0);
                    if ((va > vb) == asc) { s_key[i] = vb; s_key[ixj] = va; }
                }
                __syncthreads();
            }
        }

        // ---- Permute into depth order straight from staged arrays ----
        for (int p = tid; p < cnt; p += 256) {
            int src = (int)(s_key[p] & 0xffffffffu);
            b1[p] = a1[src];
            b2[p] = a2[src];
        }
        __syncthreads();

        // ---- Compositing (R10-proven loop) ----
        const int cg  = tid >> 6;          // channel group 0..3 (warp-uniform)
        const int pix = tid & 63;          // pixel within 16x4 tile
        const int px  = x0 + (pix & 15);
        const int py  = y0 + (pix >> 4);
        const float fpx = (float)px, fpy = (float)py;
        const int cbase = cg * 32;         // 0,32,64,96

        float A = 0.0f, D = 0.0f;
        float acc[32];
#pragma unroll
        for (int c = 0; c < 32; c++) acc[c] = 0.0f;

        for (int k = 0; k < cnt; k++) {
            float4 P1 = b1[k];
            float4 P2 = b2[k];
            float dx = fpx - P1.x;
            float dy = fpy - P1.y;
            float m  = dx * dx * P1.z + dy * dy * P1.w;
            float alpha = P2.x * __expf(-0.5f * m) * (1.0f - A);
            A += alpha;
            D += P2.y * alpha;
            if (!__any_sync(0xffffffffu, alpha > 1e-7f)) continue;
            const float4* sp = (const float4*)(spec + (size_t)__float_as_int(P2.z) * GC + cbase);
            if (cg < 3) {
#pragma unroll
                for (int q = 0; q < 8; q++) {
                    float4 v = __ldg(sp + q);
                    acc[4 * q + 0] += alpha * v.x;
                    acc[4 * q + 1] += alpha * v.y;
                    acc[4 * q + 2] += alpha * v.z;
                    acc[4 * q + 3] += alpha * v.w;
                }
            } else {
#pragma unroll
                for (int q = 0; q < 6; q++) {
                    float4 v = __ldg(sp + q);
                    acc[4 * q + 0] += alpha * v.x;
                    acc[4 * q + 1] += alpha * v.y;
                    acc[4 * q + 2] += alpha * v.z;
                    acc[4 * q + 3] += alpha * v.w;
                }
            }
        }

        if (px < GW) {   // py always < GH
            const int p = py * GW + px;
            const float bg = 1.0f - A;   // BG = 1.0
            const int nch = (cg < 3) ? 32 : 24;
#pragma unroll 8
            for (int c = 0; c < nch; c++)
                out[(size_t)(cbase + c) * GHW + p] = (acc[c] + bg) * s_tone[cbase + c];
            if (cg == 0) {
                out[(size_t)GC * GHW + p] = D;              // depth image
                out[(size_t)GC * GHW + GHW + p] = A;        // A_final
            }
        }
        __syncthreads();   // b1/b2/s_key reused next tile
    }
}

// ---------------------------------------------------------------------------
// Inputs (metadata order): positions[N,3], rotations[N,4](unused), scales[N,3],
// opacities[N], spectral_features[N,C], tone_mapping[C], intrinsics[3,3],
// extrinsics[4,4]. Output: concat(spectral[C,H,W], depth[H,W], A[H,W]) fp32.
// ---------------------------------------------------------------------------
extern "C" void kernel_launch(void* const* d_in, const int* in_sizes, int n_in,
                              void* d_out, int out_size)
{
    const float* positions  = (const float*)d_in[0];
    const float* scales     = (const float*)d_in[2];
    const float* opacities  = (const float*)d_in[3];
    const float* spectral   = (const float*)d_in[4];
    const float* tone       = (const float*)d_in[5];
    const float* intr       = (const float*)d_in[6];
    const float* extr       = (const float*)d_in[7];
    float* out = (float*)d_out;

    fused_kernel<<<NBLOCKS, 256>>>(positions, scales, opacities, spectral, tone,
                                   intr, extr, out);
}

// round 17
// speedup vs baseline: 1.2420x; 1.2420x over previous
#include <cuda_runtime.h>
#include <cuda_bf16.h>
#include <stdint.h>

#define GN 512
#define GW 332
#define GH 324
#define GHW (GW * GH)
#define GC 120
#define TSX 16
#define TSY 4
#define CUT 25.0f      // 5-sigma: exp(-12.5) ~ 3.7e-6
#define CH 32          // gaussians staged per chunk

static __device__ __forceinline__ unsigned order_float(float f) {
    unsigned u = __float_as_uint(f);
    return (u & 0x80000000u) ? ~u : (u | 0x80000000u);
}

// ---------------------------------------------------------------------------
// Single fused kernel (R10 structure). Block = 256 threads = 64 pixels
// (16x4 tile) x 4 channel groups.
//   1) project all 512 gaussians (2/thread, index order preserved)
//   2) ballot-compact those whose 5-sigma ellipse reaches the tile
//   3) bitonic-sort culled list by (depth, slot) == stable argsort; permute
//   4) composite in chunks of 32: cooperative coalesced prefetch of the 32
//      spec rows into smem (overlaid on dead staging arrays), then the
//      depth-ordered loop reads spectral data via LDS broadcast -> the
//      mid-loop L2-latency exposure of scattered LDGs is gone.
// ---------------------------------------------------------------------------
__global__ __launch_bounds__(256, 3) void fused_kernel(
    const float* __restrict__ pos,     // [N,3]
    const float* __restrict__ scales,  // [N,3]
    const float* __restrict__ ops,     // [N]
    const float* __restrict__ spec,    // [N,C]
    const float* __restrict__ tone,    // [C]
    const float* __restrict__ K,       // [3,3]
    const float* __restrict__ E,       // [4,4]
    float* __restrict__ out)           // [C*HW + HW + HW]
{
    __shared__ float4 s_stage[2 * GN];          // a1|a2 staging, later spec buf
    __shared__ float4 b1[GN], b2[GN];           // depth-sorted params
    __shared__ unsigned long long s_key[GN];
    __shared__ float s_tone[GC];
    __shared__ int   s_cnt, s_wcnt[8];

    float4* a1 = s_stage;
    float4* a2 = s_stage + GN;
    float4* s_spec = s_stage;                   // [CH][30] float4 after staging dies

    const int tid = threadIdx.x;
    if (tid < GC) s_tone[tid] = __ldg(tone + tid);
    if (tid == 0) s_cnt = 0;

    const int x0 = blockIdx.x * TSX, y0 = blockIdx.y * TSY;
    const float fx0 = (float)x0, fx1 = (float)(x0 + TSX - 1);
    const float fy0 = (float)y0, fy1 = (float)(y0 + TSY - 1);

    // Camera matrices (uniform broadcast loads).
    float E0 = __ldg(E + 0), E1 = __ldg(E + 1), E2  = __ldg(E + 2),  E3  = __ldg(E + 3);
    float E4 = __ldg(E + 4), E5 = __ldg(E + 5), E6  = __ldg(E + 6),  E7  = __ldg(E + 7);
    float E8 = __ldg(E + 8), E9 = __ldg(E + 9), E10 = __ldg(E + 10), E11 = __ldg(E + 11);
    float K0 = __ldg(K + 0), K1 = __ldg(K + 1), K2 = __ldg(K + 2);
    float K3 = __ldg(K + 3), K4 = __ldg(K + 4), K5 = __ldg(K + 5);
    float K6 = __ldg(K + 6), K7 = __ldg(K + 7), K8 = __ldg(K + 8);
    __syncthreads();

    // ---- Project + ellipse cull, 2 chunks of 256 (index order preserved) ----
#pragma unroll
    for (int c = 0; c < 2; c++) {
        const int i = c * 256 + tid;
        float p0 = __ldg(pos + 3 * i + 0), p1 = __ldg(pos + 3 * i + 1), p2 = __ldg(pos + 3 * i + 2);
        float cx = E0 * p0 + E1 * p1 + E2  * p2 + E3;
        float cy = E4 * p0 + E5 * p1 + E6  * p2 + E7;
        float cz = E8 * p0 + E9 * p1 + E10 * p2 + E11;
        float prx = K0 * cx + K1 * cy + K2 * cz;
        float pry = K3 * cx + K4 * cy + K5 * cz;
        float prz = K6 * cx + K7 * cy + K8 * cz;
        float sx = prx / (prz + 1e-6f);
        float sy = pry / (prz + 1e-6f);
        float d  = cz;

        bool valid = (d > 0.01f) && (d < 100.0f) &&
                     (sx > -100.0f) && (sx < (float)GW + 100.0f) &&
                     (sy > -100.0f) && (sy < (float)GH + 100.0f);

        float s0 = __ldg(scales + 3 * i + 0), s1v = __ldg(scales + 3 * i + 1);
        float c00 = 1.0f / (s0 * s0 + 1e-4f);
        float c11 = 1.0f / (s1v * s1v + 1e-4f);

        // Exact min mahalanobis over the tile rect: clamp center to rect.
        float nx = fminf(fmaxf(sx, fx0), fx1);
        float ny = fminf(fmaxf(sy, fy0), fy1);
        float ddx = sx - nx, ddy = sy - ny;
        float m_min = ddx * ddx * c00 + ddy * ddy * c11;

        bool keep = valid && (m_min < CUT);

        unsigned bm = __ballot_sync(0xffffffffu, keep);
        int lane = tid & 31, w = tid >> 5;
        if (lane == 0) s_wcnt[w] = __popc(bm);
        __syncthreads();
        int woff = 0;
#pragma unroll
        for (int ww = 0; ww < 8; ww++)
            if (ww < w) woff += s_wcnt[ww];
        if (keep) {
            int p = s_cnt + woff + __popc(bm & ((1u << lane) - 1u));
            a1[p] = make_float4(sx, sy, c00, c11);
            a2[p] = make_float4(__ldg(ops + i), d, __int_as_float(i), 0.0f);
            s_key[p] = ((unsigned long long)order_float(d) << 32) | (unsigned)p;
        }
        __syncthreads();
        if (tid == 0) {
            int tt = 0;
#pragma unroll
            for (int ww = 0; ww < 8; ww++) tt += s_wcnt[ww];
            s_cnt += tt;
        }
        __syncthreads();
    }
    const int cnt = s_cnt;

    // ---- Local bitonic sort by (depth, slot) ----
    int p2 = 1;
    while (p2 < cnt) p2 <<= 1;
    for (int p = cnt + tid; p < p2; p += 256)
        s_key[p] = 0xffffffffffffffffull;
    __syncthreads();
    for (int k = 2; k <= p2; k <<= 1) {
        for (int j = k >> 1; j > 0; j >>= 1) {
            if (tid < (p2 >> 1)) {
                int i = ((tid & ~(j - 1)) << 1) | (tid & (j - 1));
                int ixj = i | j;
                unsigned long long va = s_key[i], vb = s_key[ixj];
                bool asc = ((i & k) == 0);
                if ((va > vb) == asc) { s_key[i] = vb; s_key[ixj] = va; }
            }
            __syncthreads();
        }
    }

    // ---- Permute into depth order ----
    for (int p = tid; p < cnt; p += 256) {
        int slot = (int)(s_key[p] & 0xffffffffu);
        b1[p] = a1[slot];
        b2[p] = a2[slot];
    }
    __syncthreads();   // staging arrays a1/a2 are dead from here (spec buffer)

    // ---- Compositing ----
    const int cg  = tid >> 6;          // channel group 0..3 (warp-uniform)
    const int pix = tid & 63;          // pixel within 16x4 tile
    const int px  = x0 + (pix & 15);
    const int py  = y0 + (pix >> 4);
    const float fpx = (float)px, fpy = (float)py;
    const int cbase4 = cg * 8;         // float4 offset of this channel group

    float A = 0.0f, D = 0.0f;
    float acc[32];
#pragma unroll
    for (int c = 0; c < 32; c++) acc[c] = 0.0f;

    for (int base = 0; base < cnt; base += CH) {
        const int len = min(CH, cnt - base);

        // Cooperative coalesced prefetch of this chunk's spec rows.
        // len*30 float4s spread over 256 threads: full-MLP batched loads.
        const int tot = len * 30;
        for (int idx = tid; idx < tot; idx += 256) {
            const int r = idx / 30, c = idx - r * 30;
            const int id = __float_as_int(b2[base + r].z);
            s_spec[r * 30 + c] = __ldg((const float4*)(spec + (size_t)id * GC) + c);
        }
        __syncthreads();

        for (int k = 0; k < len; k++) {
            float4 P1 = b1[base + k];
            float4 P2 = b2[base + k];
            float dx = fpx - P1.x;
            float dy = fpy - P1.y;
            float m  = dx * dx * P1.z + dy * dy * P1.w;
            float alpha = P2.x * __expf(-0.5f * m) * (1.0f - A);
            A += alpha;
            D += P2.y * alpha;
            // Skip the spectral FMA block if every lane's alpha is negligible.
            if (!__any_sync(0xffffffffu, alpha > 1e-7f)) continue;
            const float4* sp = s_spec + k * 30 + cbase4;   // LDS broadcast
            if (cg < 3) {
#pragma unroll
                for (int q = 0; q < 8; q++) {
                    float4 v = sp[q];
                    acc[4 * q + 0] += alpha * v.x;
                    acc[4 * q + 1] += alpha * v.y;
                    acc[4 * q + 2] += alpha * v.z;
                    acc[4 * q + 3] += alpha * v.w;
                }
            } else {
#pragma unroll
                for (int q = 0; q < 6; q++) {
                    float4 v = sp[q];
                    acc[4 * q + 0] += alpha * v.x;
                    acc[4 * q + 1] += alpha * v.y;
                    acc[4 * q + 2] += alpha * v.z;
                    acc[4 * q + 3] += alpha * v.w;
                }
            }
        }
        __syncthreads();   // spec buffer reused next chunk
    }

    if (px < GW) {   // py always < GH (324 = 81*4)
        const int p = py * GW + px;
        const float bg = 1.0f - A;   // BG = 1.0
        const int cbase = cg * 32;
        const int nch = (cg < 3) ? 32 : 24;
#pragma unroll 8
        for (int c = 0; c < nch; c++)
            out[(size_t)(cbase + c) * GHW + p] = (acc[c] + bg) * s_tone[cbase + c];
        if (cg == 0) {
            out[(size_t)GC * GHW + p] = D;              // depth image
            out[(size_t)GC * GHW + GHW + p] = A;        // A_final
        }
    }
}

// ---------------------------------------------------------------------------
// Inputs (metadata order): positions[N,3], rotations[N,4](unused), scales[N,3],
// opacities[N], spectral_features[N,C], tone_mapping[C], intrinsics[3,3],
// extrinsics[4,4]. Output: concat(spectral[C,H,W], depth[H,W], A[H,W]) fp32.
// ---------------------------------------------------------------------------
extern "C" void kernel_launch(void* const* d_in, const int* in_sizes, int n_in,
                              void* d_out, int out_size)
{
    const float* positions  = (const float*)d_in[0];
    const float* scales     = (const float*)d_in[2];
    const float* opacities  = (const float*)d_in[3];
    const float* spectral   = (const float*)d_in[4];
    const float* tone       = (const float*)d_in[5];
    const float* intr       = (const float*)d_in[6];
    const float* extr       = (const float*)d_in[7];
    float* out = (float*)d_out;

    dim3 grid((GW + TSX - 1) / TSX, (GH + TSY - 1) / TSY);
    fused_kernel<<<grid, 256>>>(positions, scales, opacities, spectral, tone,
                                intr, extr, out);
}